// round 12
// baseline (speedup 1.0000x reference)
#include <cuda_runtime.h>

#define Tt 64
#define Ll 64
#define Bb 128
#define Hh 64
#define NSM 148
#define NTHR 256
#define NSPLIT 8
#define NTICK (Tt * Ll * NSPLIT)

#define XS_STRIDE 132
#define WS_STRIDE 36
#define SMEM_BYTES (128 * XS_STRIDE * 4 + 128 * WS_STRIDE * 4)

// Full h history h[t][l][b][u] -- no WAR hazards.
__device__ float g_h[(size_t)Tt * Ll * Bb * Hh];
// c[l][b][u] single-buffered, L2-only access.
__device__ float g_c[(size_t)Ll * Bb * Hh];
__device__ int   g_flags[Tt * Ll];
__device__ float g_partial[Tt];

typedef unsigned long long u64;

__device__ __forceinline__ u64 pack2(float a, float b) {
    u64 r; asm("mov.b64 %0, {%1, %2};" : "=l"(r) : "f"(a), "f"(b)); return r;
}
__device__ __forceinline__ void unpack2(u64 v, float& a, float& b) {
    asm("mov.b64 {%0, %1}, %2;" : "=f"(a), "=f"(b) : "l"(v));
}
__device__ __forceinline__ void fma2(u64& acc, u64 a, u64 b) {
    asm("fma.rn.f32x2 %0, %1, %2, %0;" : "+l"(acc) : "l"(a), "l"(b));
}
__device__ __forceinline__ float sigm(float x) {
    return __fdividef(1.0f, 1.0f + __expf(-x));
}
__device__ __forceinline__ int ldacq(const int* p) {
    int v; asm volatile("ld.acquire.gpu.global.b32 %0, [%1];" : "=r"(v) : "l"(p)); return v;
}
__device__ __forceinline__ void polln(const int* p) {
    while (ldacq(p) < NSPLIT) { }
}
__device__ __forceinline__ void rel_add(int* p) {
    asm volatile("red.release.gpu.global.add.s32 [%0], 1;" :: "l"(p) : "memory");
}

__global__ void init_kernel() {
    int i = blockIdx.x * blockDim.x + threadIdx.x;
    if (i < Tt * Ll) g_flags[i] = 0;
}

// 64-k FMA sweep over 2 batch rows x 4 gate-pairs.
__device__ __forceinline__ void gemm64(const float* __restrict__ Xs,
                                       const float* __restrict__ Ws,
                                       int r0, int u0, int k0, u64 acc[2][4]) {
    #pragma unroll 4
    for (int k4 = k0; k4 < k0 + 64; k4 += 4) {
        float4 av[2];
        #pragma unroll
        for (int i = 0; i < 2; i++)
            av[i] = *(const float4*)&Xs[(r0 + i) * XS_STRIDE + k4];
        #pragma unroll
        for (int q = 0; q < 4; q++) {
            u64 b2[4];
            const float* wr = Ws + (k4 + q) * WS_STRIDE + u0;
            #pragma unroll
            for (int g = 0; g < 4; g++) b2[g] = *(const u64*)(wr + g * 8);
            #pragma unroll
            for (int i = 0; i < 2; i++) {
                float a = ((const float*)&av[i])[q];
                u64 a2 = pack2(a, a);
                #pragma unroll
                for (int g = 0; g < 4; g++) fma2(acc[i][g], a2, b2[g]);
            }
        }
    }
}

// Persistent wavefront kernel, 8 CTAs per cell (cg = 8-unit group of each of
// the 4 gates -> 32 output cols per CTA). Static diag-major ticket striding
// (deadlock-free: per-CTA ticket order is monotone, deps strictly earlier).
// Adaptive split: the two 64-k GEMM halves (h_in <- l-flag, h_prev <- t-flag)
// run in flag-arrival order; separate accumulators keep summation order
// fixed => bit-deterministic output.
__global__ void __launch_bounds__(NTHR, 1) wave_kernel(
    const float* __restrict__ x,  const float* __restrict__ W0,
    const float* __restrict__ b0, const float* __restrict__ Wl,
    const float* __restrict__ bl)
{
    extern __shared__ float smem[];
    float* Xs = smem;                       // [128][XS_STRIDE] cols 0-63 h_in, 64-127 h_prev
    float* Ws = smem + 128 * XS_STRIDE;     // [128][WS_STRIDE] col j = g*8+u
    __shared__ int sh_first;

    const int tid = threadIdx.x;
    const int r0  = (tid >> 2) * 2;   // 2 batch rows / thread
    const int u0  = (tid & 3) * 2;    // 2 adjacent units (of 8-unit group)
    const int srow = tid >> 1;        // staging row, 0..127
    const int shalf = tid & 1;

    for (int w = blockIdx.x; w < NTICK; w += gridDim.x) {
        // ---- decode ticket -> (t, l, cg), diagonal-major ----
        int rem = w, d = 0;
        for (;; ++d) {
            int nd8 = min(min(d + 1, 127 - d), 64) * NSPLIT;
            if (rem < nd8) break;
            rem -= nd8;
        }
        const int cg   = rem & 7;
        const int cell = rem >> 3;
        const int t    = ((d > 63) ? (d - 63) : 0) + cell;
        const int l    = d - t;

        __syncthreads();   // prev iter smem reusable

        // ---- stage W tile: 128 rows x 32 cols (no deps; overlaps spins) ----
        // 2 threads/row; shalf covers gates {0,1} or {2,3}: 8 floats per gate.
        if (l > 0) {
            const float* wrow = Wl + (size_t)(l - 1) * 128 * 256 + (size_t)srow * 256 + cg * 8;
            float* dst = Ws + srow * WS_STRIDE + shalf * 16;
            #pragma unroll
            for (int e = 0; e < 2; e++) {
                const float2* s2 = (const float2*)(wrow + (shalf * 2 + e) * 64);
                float2* d2 = (float2*)(dst + e * 8);
                #pragma unroll
                for (int q = 0; q < 4; q++) d2[q] = s2[q];
            }
        } else if (srow < 68) {
            float* dst = Ws + srow * WS_STRIDE + shalf * 16;
            if (srow < 65) {
                const float* wrow = W0 + (size_t)srow * 256 + cg * 8;
                #pragma unroll
                for (int e = 0; e < 2; e++) {
                    const float2* s2 = (const float2*)(wrow + (shalf * 2 + e) * 64);
                    float2* d2 = (float2*)(dst + e * 8);
                    #pragma unroll
                    for (int q = 0; q < 4; q++) d2[q] = s2[q];
                }
            } else {
                float2 z = make_float2(0.f, 0.f);
                float2* d2 = (float2*)dst;
                #pragma unroll
                for (int q = 0; q < 8; q++) d2[q] = z;
            }
        }

        float2 bpre[4];
        {
            const float* bias = (l == 0) ? b0 : (bl + (l - 1) * 256);
            #pragma unroll
            for (int g = 0; g < 4; g++)
                bpre[g] = *(const float2*)(bias + g * 64 + cg * 8 + u0);
        }

        // accI seeded with bias; accP zero.  z = (bias + zI) + zP (fixed order).
        u64 accI[2][4], accP[2][4];
        #pragma unroll
        for (int g = 0; g < 4; g++) {
            u64 bs = pack2(bpre[g].x, bpre[g].y);
            #pragma unroll
            for (int i = 0; i < 2; i++) { accI[i][g] = bs; accP[i][g] = 0ULL; }
        }

        const float* hin_base   = (l > 0) ? &g_h[((size_t)t * Ll + (l - 1)) * Bb * Hh] : (const float*)0;
        const float* hprev_base = (t > 0) ? &g_h[((size_t)(t - 1) * Ll + l) * Bb * Hh] : (const float*)0;

        if (l == 0) {
            // ---- GEMM over [x | h_prev | 0pad], 68 k ----
            if (tid == 0 && t > 0) polln(&g_flags[(t - 1) * Ll + l]);
            __syncthreads();
            {
                float* dst = Xs + srow * XS_STRIDE;
                int c0 = shalf * 34;
                #pragma unroll 2
                for (int c = c0; c < c0 + 34; c++) {
                    float v = 0.f;
                    if (c == 0) v = x[srow * Tt + t];
                    else if (c < 65 && t > 0) v = hprev_base[srow * Hh + (c - 1)];
                    dst[c] = v;
                }
            }
            __syncthreads();
            gemm64(Xs, Ws, r0, u0, 0, accI);
            {
                float4 av[2];
                #pragma unroll
                for (int i = 0; i < 2; i++)
                    av[i] = *(const float4*)&Xs[(r0 + i) * XS_STRIDE + 64];
                #pragma unroll
                for (int q = 0; q < 4; q++) {
                    u64 b2[4];
                    const float* wr = Ws + (64 + q) * WS_STRIDE + u0;
                    #pragma unroll
                    for (int g = 0; g < 4; g++) b2[g] = *(const u64*)(wr + g * 8);
                    #pragma unroll
                    for (int i = 0; i < 2; i++) {
                        float a = ((const float*)&av[i])[q];
                        u64 a2 = pack2(a, a);
                        #pragma unroll
                        for (int g = 0; g < 4; g++) fma2(accI[i][g], a2, b2[g]);
                    }
                }
            }
        } else if (t == 0) {
            // ---- only h_in half ----
            if (tid == 0) polln(&g_flags[t * Ll + (l - 1)]);
            __syncthreads();
            {
                const float4* s = (const float4*)(hin_base + srow * Hh + shalf * 32);
                float4* dt = (float4*)(Xs + srow * XS_STRIDE + shalf * 32);
                #pragma unroll
                for (int q = 0; q < 8; q++) dt[q] = s[q];
            }
            __syncthreads();
            gemm64(Xs, Ws, r0, u0, 0, accI);
        } else {
            // ---- adaptive dual-half path ----
            const int* fI = &g_flags[t * Ll + (l - 1)];
            const int* fP = &g_flags[(t - 1) * Ll + l];
            if (tid == 0) {
                int a, b;
                for (;;) {
                    a = ldacq(fI); b = ldacq(fP);
                    if (a >= NSPLIT || b >= NSPLIT) break;
                }
                sh_first = (a >= NSPLIT) ? ((b >= NSPLIT) ? 2 : 0) : 1;
            }
            __syncthreads();
            const int first = sh_first;

            if (first == 2) {
                // both ready: fused full-128k path
                {
                    const float* src = (shalf == 0) ? (hin_base + srow * Hh)
                                                    : (hprev_base + srow * Hh);
                    float* dt = Xs + srow * XS_STRIDE + shalf * 64;
                    #pragma unroll
                    for (int q = 0; q < 16; q++)
                        ((float4*)dt)[q] = ((const float4*)src)[q];
                }
                __syncthreads();
                gemm64(Xs, Ws, r0, u0, 0, accI);
                gemm64(Xs, Ws, r0, u0, 64, accP);
            } else if (first == 0) {
                // h_in first
                {
                    const float4* s = (const float4*)(hin_base + srow * Hh + shalf * 32);
                    float4* dt = (float4*)(Xs + srow * XS_STRIDE + shalf * 32);
                    #pragma unroll
                    for (int q = 0; q < 8; q++) dt[q] = s[q];
                }
                __syncthreads();
                gemm64(Xs, Ws, r0, u0, 0, accI);
                if (tid == 0) polln(fP);
                __syncthreads();
                {
                    const float4* s = (const float4*)(hprev_base + srow * Hh + shalf * 32);
                    float4* dt = (float4*)(Xs + srow * XS_STRIDE + 64 + shalf * 32);
                    #pragma unroll
                    for (int q = 0; q < 8; q++) dt[q] = s[q];
                }
                __syncthreads();
                gemm64(Xs, Ws, r0, u0, 64, accP);
            } else {
                // h_prev first
                {
                    const float4* s = (const float4*)(hprev_base + srow * Hh + shalf * 32);
                    float4* dt = (float4*)(Xs + srow * XS_STRIDE + 64 + shalf * 32);
                    #pragma unroll
                    for (int q = 0; q < 8; q++) dt[q] = s[q];
                }
                __syncthreads();
                gemm64(Xs, Ws, r0, u0, 64, accP);
                if (tid == 0) polln(fI);
                __syncthreads();
                {
                    const float4* s = (const float4*)(hin_base + srow * Hh + shalf * 32);
                    float4* dt = (float4*)(Xs + srow * XS_STRIDE + shalf * 32);
                    #pragma unroll
                    for (int q = 0; q < 8; q++) dt[q] = s[q];
                }
                __syncthreads();
                gemm64(Xs, Ws, r0, u0, 0, accI);
            }
        }

        // ---- gates epilogue: z = accI + accP (fixed order) ----
        float* cptr = &g_c[(size_t)l * Bb * Hh];
        float* hout = &g_h[((size_t)t * Ll + l) * Bb * Hh];
        #pragma unroll
        for (int i = 0; i < 2; i++) {
            int row = r0 + i;
            int off = row * Hh + cg * 8 + u0;
            float z0[4], z1[4];
            #pragma unroll
            for (int g = 0; g < 4; g++) {
                float iA, iB, pA, pB;
                unpack2(accI[i][g], iA, iB);
                unpack2(accP[i][g], pA, pB);
                z0[g] = iA + pA; z1[g] = iB + pB;
            }
            float cp0 = 0.f, cp1 = 0.f;
            if (t > 0) {
                float2 cp = __ldcg((const float2*)(cptr + off));
                cp0 = cp.x; cp1 = cp.y;
            }
            float c20 = cp0 * sigm(z0[2]) + sigm(z0[0]) * tanhf(z0[1]);
            float c21 = cp1 * sigm(z1[2]) + sigm(z1[0]) * tanhf(z1[1]);
            float h20 = tanhf(c20) * sigm(z0[3]);
            float h21 = tanhf(c21) * sigm(z1[3]);
            __stcg((float2*)(cptr + off), make_float2(c20, c21));
            *(float2*)(hout + off) = make_float2(h20, h21);
        }

        __syncthreads();   // all stores issued
        if (tid == 0) rel_add(&g_flags[t * Ll + l]);
    }
}

// pred[b,t] = relu(h[t][63][b][:] . Wd[t] + bd[t]); per-t squared-error partials.
__global__ void dense_kernel(const float* __restrict__ labels, const float* __restrict__ Wd,
                             const float* __restrict__ bd, float* __restrict__ out)
{
    int t = blockIdx.x;
    int b = threadIdx.x;
    __shared__ float wd[64];
    __shared__ float red[128];
    if (b < 64) wd[b] = Wd[t * 64 + b];
    __syncthreads();
    const float* hrow = &g_h[(((size_t)t * Ll + 63) * Bb + b) * Hh];
    float acc = 0.f;
    #pragma unroll
    for (int u = 0; u < 64; u++) acc += hrow[u] * wd[u];
    float p = acc + bd[t];
    p = (p > 0.f) ? p : 0.f;
    out[b * 64 + t] = p;
    float e = labels[b * 64 + t] - p;
    red[b] = e * e;
    __syncthreads();
    for (int s = 64; s > 0; s >>= 1) {
        if (b < s) red[b] += red[b + s];
        __syncthreads();
    }
    if (b == 0) g_partial[t] = red[0];
}

__global__ void loss_kernel(float* out, int out_size)
{
    __shared__ float red[64];
    int tid = threadIdx.x;
    red[tid] = g_partial[tid];
    __syncthreads();
    for (int s = 32; s > 0; s >>= 1) {
        if (tid < s) red[tid] += red[tid + s];
        __syncthreads();
    }
    if (tid == 0 && out_size > Bb * Tt) out[Bb * Tt] = red[0] / (float)(Bb * Tt);
}

extern "C" void kernel_launch(void* const* d_in, const int* in_sizes, int n_in,
                              void* d_out, int out_size) {
    const float* x      = (const float*)d_in[0];
    const float* labels = (const float*)d_in[1];
    const float* W0     = (const float*)d_in[2];
    const float* b0     = (const float*)d_in[3];
    const float* Wl     = (const float*)d_in[4];
    const float* bl     = (const float*)d_in[5];
    const float* Wd     = (const float*)d_in[6];
    const float* bd     = (const float*)d_in[7];
    float* out = (float*)d_out;

    cudaFuncSetAttribute(wave_kernel, cudaFuncAttributeMaxDynamicSharedMemorySize, SMEM_BYTES);

    init_kernel<<<16, 256>>>();
    wave_kernel<<<NSM, NTHR, SMEM_BYTES>>>(x, W0, b0, Wl, bl);
    dense_kernel<<<64, 128>>>(labels, Wd, bd, out);
    loss_kernel<<<1, 64>>>(out, out_size);
}

// round 14
// speedup vs baseline: 1.7633x; 1.7633x over previous
#include <cuda_runtime.h>

#define Tt 64
#define Ll 64
#define Bb 128
#define Hh 64
#define NSM 148
#define NTHR 256
#define NSPLIT 4
#define NTICK (Tt * Ll * NSPLIT)

// dynamic smem: XsA 32KB | XsB 32KB | Ws 32KB | mbarriers
#define XA_OFF 0
#define XB_OFF 8192
#define WS_OFF 16384
#define SMEM_FLOATS 24576
#define MBAR_OFF (SMEM_FLOATS * 4)          // byte offset of mbarrier area
#define SMEM_BYTES (SMEM_FLOATS * 4 + 64)

typedef unsigned int u32;
typedef unsigned long long u64;

// Full h history h[t][l][b][u] -- no WAR hazards. 32KB per (t,l) tile.
__device__ float g_h[(size_t)Tt * Ll * Bb * Hh];
// c[l][b][u] single-buffered, L2-only access.
__device__ float g_c[(size_t)Ll * Bb * Hh];
// W_tiled[l][cg][k 0..127][j 0..63]: contiguous 32KB tile per (l,cg).
//  l>0 : k = rows of Wl[l-1] (0-63 h_in, 64-127 h_prev), j = g*16+u local col
//  l==0: k 0-63 = W0 rows 1..64 (h_prev), k64 = W0 row 0 (x), k 65-127 = 0
__device__ float g_wt[(size_t)Ll * 4 * 128 * 64];
__device__ int   g_flags[Tt * Ll];
__device__ float g_partial[Tt];

__device__ __forceinline__ u64 pack2(float a, float b) {
    u64 r; asm("mov.b64 %0, {%1, %2};" : "=l"(r) : "f"(a), "f"(b)); return r;
}
__device__ __forceinline__ void unpack2(u64 v, float& a, float& b) {
    asm("mov.b64 {%0, %1}, %2;" : "=f"(a), "=f"(b) : "l"(v));
}
__device__ __forceinline__ void fma2(u64& acc, u64 a, u64 b) {
    asm("fma.rn.f32x2 %0, %1, %2, %0;" : "+l"(acc) : "l"(a), "l"(b));
}
__device__ __forceinline__ float sigm(float x) {
    return __fdividef(1.0f, 1.0f + __expf(-x));
}
__device__ __forceinline__ int ldacq(const int* p) {
    int v; asm volatile("ld.acquire.gpu.global.b32 %0, [%1];" : "=r"(v) : "l"(p)); return v;
}
__device__ __forceinline__ void polln(const int* p) {
    while (ldacq(p) < NSPLIT) { }
}
__device__ __forceinline__ void rel_add(int* p) {
    asm volatile("red.release.gpu.global.add.s32 [%0], 1;" :: "l"(p) : "memory");
}
__device__ __forceinline__ void mbar_init(u32 mbar, u32 cnt) {
    asm volatile("mbarrier.init.shared.b64 [%0], %1;" :: "r"(mbar), "r"(cnt) : "memory");
}
__device__ __forceinline__ void mbar_expect(u32 mbar, u32 bytes) {
    asm volatile("mbarrier.arrive.expect_tx.shared.b64 _, [%0], %1;" :: "r"(mbar), "r"(bytes) : "memory");
}
__device__ __forceinline__ void bulk_g2s(u32 dst, const void* src, u32 bytes, u32 mbar) {
    asm volatile("cp.async.bulk.shared::cluster.global.mbarrier::complete_tx::bytes [%0], [%1], %2, [%3];"
                 :: "r"(dst), "l"(src), "r"(bytes), "r"(mbar) : "memory");
}
__device__ __forceinline__ void mbar_wait(u32 mbar, u32 parity) {
    u32 done;
    do {
        asm volatile("{\n\t.reg .pred p;\n\t"
                     "mbarrier.try_wait.parity.acquire.cta.shared::cta.b64 p, [%1], %2, 0x989680;\n\t"
                     "selp.b32 %0, 1, 0, p;\n\t}"
                     : "=r"(done) : "r"(mbar), "r"(parity) : "memory");
    } while (!done);
}

__global__ void init_kernel() {
    int i = blockIdx.x * blockDim.x + threadIdx.x;
    if (i < Tt * Ll) g_flags[i] = 0;
}

// Build W_tiled (2M elements).
__global__ void wtile_kernel(const float* __restrict__ W0, const float* __restrict__ Wl) {
    int idx = blockIdx.x * blockDim.x + threadIdx.x;   // < 64*4*128*64
    int j   = idx & 63;
    int k   = (idx >> 6) & 127;
    int cg  = (idx >> 13) & 3;
    int l   = idx >> 15;
    int col = (j >> 4) * 64 + cg * 16 + (j & 15);
    float v;
    if (l > 0) {
        v = Wl[(size_t)(l - 1) * 128 * 256 + (size_t)k * 256 + col];
    } else {
        if (k < 64)       v = W0[(size_t)(k + 1) * 256 + col];
        else if (k == 64) v = W0[col];
        else              v = 0.f;
    }
    g_wt[idx] = v;
}

// 64-k FMA sweep: acc += Xh[row][kk] * Wb[kk][col], Xh [128][64], Wb = Ws+k0*64
__device__ __forceinline__ void gemm64(const float* __restrict__ Xh,
                                       const float* __restrict__ Wb,
                                       int r0, int u0, u64 acc[4][4]) {
    #pragma unroll 4
    for (int k4 = 0; k4 < 64; k4 += 4) {
        float4 av[4];
        #pragma unroll
        for (int i = 0; i < 4; i++)
            av[i] = *(const float4*)&Xh[(r0 + i) * 64 + k4];
        #pragma unroll
        for (int q = 0; q < 4; q++) {
            u64 b2[4];
            const float* wr = Wb + (k4 + q) * 64 + u0;
            #pragma unroll
            for (int g = 0; g < 4; g++) b2[g] = *(const u64*)(wr + g * 16);
            #pragma unroll
            for (int i = 0; i < 4; i++) {
                float a = ((const float*)&av[i])[q];
                u64 a2 = pack2(a, a);
                #pragma unroll
                for (int g = 0; g < 4; g++) fma2(acc[i][g], a2, b2[g]);
            }
        }
    }
}

// Persistent wavefront kernel: 4 CTAs/cell, static diag-major striding,
// adaptive half order, all tile staging via cp.async.bulk (UBLKCP) + mbarrier.
__global__ void __launch_bounds__(NTHR, 1) wave_kernel(
    const float* __restrict__ x,  const float* __restrict__ b0,
    const float* __restrict__ bl)
{
    extern __shared__ float smem[];
    float* XsA = smem + XA_OFF;     // [128][64] k 0-63
    float* XsB = smem + XB_OFF;     // [128][64] k 64-127
    float* Ws  = smem + WS_OFF;     // [128][64]
    __shared__ int sh_first;

    u32 sbase = (u32)__cvta_generic_to_shared(smem);
    const u32 mW  = sbase + MBAR_OFF;
    const u32 mX0 = sbase + MBAR_OFF + 8;
    const u32 mX1 = sbase + MBAR_OFF + 16;
    const u32 aXA = sbase + XA_OFF * 4;
    const u32 aXB = sbase + XB_OFF * 4;
    const u32 aWS = sbase + WS_OFF * 4;

    const int tid = threadIdx.x;
    const int r0  = (tid >> 3) * 4;   // 4 batch rows / thread
    const int u0  = (tid & 7) * 2;    // 2 adjacent units (of 16-unit group)

    // one-time: zero tiles (finite garbage guarantees) + init mbarriers
    {
        float4 z = make_float4(0.f, 0.f, 0.f, 0.f);
        for (int i = tid; i < SMEM_FLOATS / 4; i += NTHR) ((float4*)smem)[i] = z;
        if (tid == 0) {
            mbar_init(mW, 1); mbar_init(mX0, 1); mbar_init(mX1, 1);
            asm volatile("fence.proxy.async.shared::cta;" ::: "memory");
        }
    }
    __syncthreads();
    u32 pw = 0, p0 = 0, p1 = 0;

    for (int w = blockIdx.x; w < NTICK; w += gridDim.x) {
        // ---- decode ticket -> (t, l, cg), diagonal-major ----
        int rem = w, d = 0;
        for (;; ++d) {
            int nd4 = min(min(d + 1, 127 - d), 64) * NSPLIT;
            if (rem < nd4) break;
            rem -= nd4;
        }
        const int cg   = rem & 3;
        const int cell = rem >> 2;
        const int t    = ((d > 63) ? (d - 63) : 0) + cell;
        const int l    = d - t;

        // ---- stage W tile: one 32KB bulk (no deps) ----
        if (tid == 0) {
            mbar_expect(mW, 32768);
            bulk_g2s(aWS, &g_wt[((size_t)l * 4 + cg) * 8192], 32768, mW);
        }

        float2 bpre[4];
        {
            const float* bias = (l == 0) ? b0 : (bl + (l - 1) * 256);
            #pragma unroll
            for (int g = 0; g < 4; g++)
                bpre[g] = *(const float2*)(bias + g * 64 + cg * 16 + u0);
        }
        u64 accI[4][4], accP[4][4];
        #pragma unroll
        for (int g = 0; g < 4; g++) {
            u64 bs = pack2(bpre[g].x, bpre[g].y);
            #pragma unroll
            for (int i = 0; i < 4; i++) { accI[i][g] = bs; accP[i][g] = 0ULL; }
        }

        const float* hin_base   = (l > 0) ? &g_h[((size_t)t * Ll + (l - 1)) * Bb * Hh] : (const float*)0;
        const float* hprev_base = (t > 0) ? &g_h[((size_t)(t - 1) * Ll + l) * Bb * Hh] : (const float*)0;

        if (l == 0) {
            // X = [h_prev (A) | x at B.col0 | zeros]; W_tiled[0] matches.
            if (tid == 0 && t > 0) {
                polln(&g_flags[(t - 1) * Ll + l]);
                mbar_expect(mX0, 32768);
                bulk_g2s(aXA, hprev_base, 32768, mX0);
            }
            if (tid < 128) XsB[tid * 64] = x[tid * Tt + t];
            if (t == 0) {
                // zero XsA (stale h values would multiply real weights)
                float4 z = make_float4(0.f, 0.f, 0.f, 0.f);
                for (int i = tid; i < 2048; i += NTHR) ((float4*)XsA)[i] = z;
            }
            __syncthreads();                 // x column + optional zeroing visible
            mbar_wait(mW, pw); pw ^= 1;
            if (t > 0) { mbar_wait(mX0, p0); p0 ^= 1; gemm64(XsA, Ws, r0, u0, accI); }
            // x term: Ws row 64 holds W0 row 0
            {
                u64 b2[4];
                #pragma unroll
                for (int g = 0; g < 4; g++) b2[g] = *(const u64*)(Ws + 64 * 64 + g * 16 + u0);
                #pragma unroll
                for (int i = 0; i < 4; i++) {
                    float a = XsB[(r0 + i) * 64];
                    u64 a2 = pack2(a, a);
                    #pragma unroll
                    for (int g = 0; g < 4; g++) fma2(accI[i][g], a2, b2[g]);
                }
            }
        } else if (t == 0) {
            // only h_in half
            if (tid == 0) {
                polln(&g_flags[t * Ll + (l - 1)]);
                mbar_expect(mX0, 32768);
                bulk_g2s(aXA, hin_base, 32768, mX0);
            }
            mbar_wait(mW, pw); pw ^= 1;
            mbar_wait(mX0, p0); p0 ^= 1;
            gemm64(XsA, Ws, r0, u0, accI);
        } else {
            // adaptive dual-half
            const int* fI = &g_flags[t * Ll + (l - 1)];
            const int* fP = &g_flags[(t - 1) * Ll + l];
            if (tid == 0) {
                int a, b;
                for (;;) {
                    a = ldacq(fI); b = ldacq(fP);
                    if (a >= NSPLIT || b >= NSPLIT) break;
                }
                int first = (a >= NSPLIT) ? ((b >= NSPLIT) ? 2 : 0) : 1;
                sh_first = first;
                if (first == 2) {
                    mbar_expect(mX0, 65536);
                    bulk_g2s(aXA, hin_base, 32768, mX0);
                    bulk_g2s(aXB, hprev_base, 32768, mX0);
                } else if (first == 0) {
                    mbar_expect(mX0, 32768);
                    bulk_g2s(aXA, hin_base, 32768, mX0);
                } else {
                    mbar_expect(mX0, 32768);
                    bulk_g2s(aXB, hprev_base, 32768, mX0);
                }
            }
            __syncthreads();
            const int first = sh_first;
            mbar_wait(mW, pw); pw ^= 1;
            mbar_wait(mX0, p0); p0 ^= 1;
            if (first == 2) {
                gemm64(XsA, Ws, r0, u0, accI);
                gemm64(XsB, Ws + 64 * 64, r0, u0, accP);
            } else if (first == 0) {
                gemm64(XsA, Ws, r0, u0, accI);
                if (tid == 0) {
                    polln(fP);
                    mbar_expect(mX1, 32768);
                    bulk_g2s(aXB, hprev_base, 32768, mX1);
                }
                mbar_wait(mX1, p1); p1 ^= 1;
                gemm64(XsB, Ws + 64 * 64, r0, u0, accP);
            } else {
                gemm64(XsB, Ws + 64 * 64, r0, u0, accP);
                if (tid == 0) {
                    polln(fI);
                    mbar_expect(mX1, 32768);
                    bulk_g2s(aXA, hin_base, 32768, mX1);
                }
                mbar_wait(mX1, p1); p1 ^= 1;
                gemm64(XsA, Ws, r0, u0, accI);
            }
        }

        // ---- gates epilogue: z = (bias + zI) + zP (fixed order) ----
        float* cptr = &g_c[(size_t)l * Bb * Hh];
        float* hout = &g_h[((size_t)t * Ll + l) * Bb * Hh];
        #pragma unroll
        for (int i = 0; i < 4; i++) {
            int row = r0 + i;
            int off = row * Hh + cg * 16 + u0;
            float z0[4], z1[4];
            #pragma unroll
            for (int g = 0; g < 4; g++) {
                float iA, iB, pA, pB;
                unpack2(accI[i][g], iA, iB);
                unpack2(accP[i][g], pA, pB);
                z0[g] = iA + pA; z1[g] = iB + pB;
            }
            float cp0 = 0.f, cp1 = 0.f;
            if (t > 0) {
                float2 cp = __ldcg((const float2*)(cptr + off));
                cp0 = cp.x; cp1 = cp.y;
            }
            float c20 = cp0 * sigm(z0[2]) + sigm(z0[0]) * tanhf(z0[1]);
            float c21 = cp1 * sigm(z1[2]) + sigm(z1[0]) * tanhf(z1[1]);
            float h20 = tanhf(c20) * sigm(z0[3]);
            float h21 = tanhf(c21) * sigm(z1[3]);
            __stcg((float2*)(cptr + off), make_float2(c20, c21));
            *(float2*)(hout + off) = make_float2(h20, h21);
        }

        __syncthreads();   // all stores issued; also gates smem reuse next iter
        if (tid == 0) rel_add(&g_flags[t * Ll + l]);
    }
}

// pred[b,t] = relu(h[t][63][b][:] . Wd[t] + bd[t]); per-t squared-error partials.
__global__ void dense_kernel(const float* __restrict__ labels, const float* __restrict__ Wd,
                             const float* __restrict__ bd, float* __restrict__ out)
{
    int t = blockIdx.x;
    int b = threadIdx.x;
    __shared__ float wd[64];
    __shared__ float red[128];
    if (b < 64) wd[b] = Wd[t * 64 + b];
    __syncthreads();
    const float* hrow = &g_h[(((size_t)t * Ll + 63) * Bb + b) * Hh];
    float acc = 0.f;
    #pragma unroll
    for (int u = 0; u < 64; u++) acc += hrow[u] * wd[u];
    float p = acc + bd[t];
    p = (p > 0.f) ? p : 0.f;
    out[b * 64 + t] = p;
    float e = labels[b * 64 + t] - p;
    red[b] = e * e;
    __syncthreads();
    for (int s = 64; s > 0; s >>= 1) {
        if (b < s) red[b] += red[b + s];
        __syncthreads();
    }
    if (b == 0) g_partial[t] = red[0];
}

__global__ void loss_kernel(float* out, int out_size)
{
    __shared__ float red[64];
    int tid = threadIdx.x;
    red[tid] = g_partial[tid];
    __syncthreads();
    for (int s = 32; s > 0; s >>= 1) {
        if (tid < s) red[tid] += red[tid + s];
        __syncthreads();
    }
    if (tid == 0 && out_size > Bb * Tt) out[Bb * Tt] = red[0] / (float)(Bb * Tt);
}

extern "C" void kernel_launch(void* const* d_in, const int* in_sizes, int n_in,
                              void* d_out, int out_size) {
    const float* x      = (const float*)d_in[0];
    const float* labels = (const float*)d_in[1];
    const float* W0     = (const float*)d_in[2];
    const float* b0     = (const float*)d_in[3];
    const float* Wl     = (const float*)d_in[4];
    const float* bl     = (const float*)d_in[5];
    const float* Wd     = (const float*)d_in[6];
    const float* bd     = (const float*)d_in[7];
    float* out = (float*)d_out;

    cudaFuncSetAttribute(wave_kernel, cudaFuncAttributeMaxDynamicSharedMemorySize, SMEM_BYTES);

    init_kernel<<<16, 256>>>();
    wtile_kernel<<<8192, 256>>>(W0, Wl);
    wave_kernel<<<NSM, NTHR, SMEM_BYTES>>>(x, b0, bl);
    dense_kernel<<<64, 128>>>(labels, Wd, bd, out);
    loss_kernel<<<1, 64>>>(out, out_size);
}

// round 15
// speedup vs baseline: 1.8706x; 1.0609x over previous
#include <cuda_runtime.h>

#define Tt 64
#define Ll 64
#define Bb 128
#define Hh 64
#define NSM 148
#define NCTA (2 * NSM)
#define NTHR 256
#define NSPLIT 4
#define NTICK (Tt * Ll * NSPLIT)

// dynamic smem: XsA 32KB | XsB 32KB | Ws 32KB | mbarriers
#define XA_OFF 0
#define XB_OFF 8192
#define WS_OFF 16384
#define SMEM_FLOATS 24576
#define MBAR_OFF (SMEM_FLOATS * 4)          // byte offset of mbarrier area
#define SMEM_BYTES (SMEM_FLOATS * 4 + 64)

typedef unsigned int u32;
typedef unsigned long long u64;

// Full h history h[t][l][b][u] -- no WAR hazards. 32KB per (t,l) tile.
__device__ float g_h[(size_t)Tt * Ll * Bb * Hh];
// c[l][b][u] single-buffered, L2-only access.
__device__ float g_c[(size_t)Ll * Bb * Hh];
// W_tiled[l][cg][k 0..127][j 0..63]: contiguous 32KB tile per (l,cg).
//  l>0 : k = rows of Wl[l-1] (0-63 h_in, 64-127 h_prev), j = g*16+u local col
//  l==0: k 0-63 = W0 rows 1..64 (h_prev), k64 = W0 row 0 (x), k 65-127 = 0
__device__ float g_wt[(size_t)Ll * 4 * 128 * 64];
__device__ int   g_flags[Tt * Ll];
__device__ float g_partial[Tt];

__device__ __forceinline__ u64 pack2(float a, float b) {
    u64 r; asm("mov.b64 %0, {%1, %2};" : "=l"(r) : "f"(a), "f"(b)); return r;
}
__device__ __forceinline__ void unpack2(u64 v, float& a, float& b) {
    asm("mov.b64 {%0, %1}, %2;" : "=f"(a), "=f"(b) : "l"(v));
}
__device__ __forceinline__ void fma2(u64& acc, u64 a, u64 b) {
    asm("fma.rn.f32x2 %0, %1, %2, %0;" : "+l"(acc) : "l"(a), "l"(b));
}
__device__ __forceinline__ float sigm(float x) {
    return __fdividef(1.0f, 1.0f + __expf(-x));
}
__device__ __forceinline__ int ldacq(const int* p) {
    int v; asm volatile("ld.acquire.gpu.global.b32 %0, [%1];" : "=r"(v) : "l"(p)); return v;
}
__device__ __forceinline__ void polln(const int* p) {
    while (ldacq(p) < NSPLIT) { }
}
__device__ __forceinline__ void rel_add(int* p) {
    asm volatile("red.release.gpu.global.add.s32 [%0], 1;" :: "l"(p) : "memory");
}
__device__ __forceinline__ void mbar_init(u32 mbar, u32 cnt) {
    asm volatile("mbarrier.init.shared.b64 [%0], %1;" :: "r"(mbar), "r"(cnt) : "memory");
}
__device__ __forceinline__ void mbar_expect(u32 mbar, u32 bytes) {
    asm volatile("mbarrier.arrive.expect_tx.shared.b64 _, [%0], %1;" :: "r"(mbar), "r"(bytes) : "memory");
}
__device__ __forceinline__ void bulk_g2s(u32 dst, const void* src, u32 bytes, u32 mbar) {
    asm volatile("cp.async.bulk.shared::cluster.global.mbarrier::complete_tx::bytes [%0], [%1], %2, [%3];"
                 :: "r"(dst), "l"(src), "r"(bytes), "r"(mbar) : "memory");
}
__device__ __forceinline__ void mbar_wait(u32 mbar, u32 parity) {
    u32 done;
    do {
        asm volatile("{\n\t.reg .pred p;\n\t"
                     "mbarrier.try_wait.parity.acquire.cta.shared::cta.b64 p, [%1], %2, 0x989680;\n\t"
                     "selp.b32 %0, 1, 0, p;\n\t}"
                     : "=r"(done) : "r"(mbar), "r"(parity) : "memory");
    } while (!done);
}

__global__ void init_kernel() {
    int i = blockIdx.x * blockDim.x + threadIdx.x;
    if (i < Tt * Ll) g_flags[i] = 0;
}

// Build W_tiled (2M elements).
__global__ void wtile_kernel(const float* __restrict__ W0, const float* __restrict__ Wl) {
    int idx = blockIdx.x * blockDim.x + threadIdx.x;   // < 64*4*128*64
    int j   = idx & 63;
    int k   = (idx >> 6) & 127;
    int cg  = (idx >> 13) & 3;
    int l   = idx >> 15;
    int col = (j >> 4) * 64 + cg * 16 + (j & 15);
    float v;
    if (l > 0) {
        v = Wl[(size_t)(l - 1) * 128 * 256 + (size_t)k * 256 + col];
    } else {
        if (k < 64)       v = W0[(size_t)(k + 1) * 256 + col];
        else if (k == 64) v = W0[col];
        else              v = 0.f;
    }
    g_wt[idx] = v;
}

// 64-k FMA sweep: acc += Xh[row][kk] * Wb[kk][col], Xh [128][64], Wb = Ws+k0*64
__device__ __forceinline__ void gemm64(const float* __restrict__ Xh,
                                       const float* __restrict__ Wb,
                                       int r0, int u0, u64 acc[4][4]) {
    #pragma unroll 4
    for (int k4 = 0; k4 < 64; k4 += 4) {
        float4 av[4];
        #pragma unroll
        for (int i = 0; i < 4; i++)
            av[i] = *(const float4*)&Xh[(r0 + i) * 64 + k4];
        #pragma unroll
        for (int q = 0; q < 4; q++) {
            u64 b2[4];
            const float* wr = Wb + (k4 + q) * 64 + u0;
            #pragma unroll
            for (int g = 0; g < 4; g++) b2[g] = *(const u64*)(wr + g * 16);
            #pragma unroll
            for (int i = 0; i < 4; i++) {
                float a = ((const float*)&av[i])[q];
                u64 a2 = pack2(a, a);
                #pragma unroll
                for (int g = 0; g < 4; g++) fma2(acc[i][g], a2, b2[g]);
            }
        }
    }
}

// Persistent wavefront kernel: 4 CTAs/cell, static diag-major striding,
// adaptive half order, all tile staging via cp.async.bulk + mbarrier.
// 2 CTAs resident per SM: 296 resident CTAs > widest diagonal (256 tickets),
// so no diagonal wave-quantizes, and spins overlap with co-CTA compute.
__global__ void __launch_bounds__(NTHR, 2) wave_kernel(
    const float* __restrict__ x,  const float* __restrict__ b0,
    const float* __restrict__ bl)
{
    extern __shared__ float smem[];
    float* XsA = smem + XA_OFF;     // [128][64] k 0-63
    float* XsB = smem + XB_OFF;     // [128][64] k 64-127
    float* Ws  = smem + WS_OFF;     // [128][64]
    __shared__ int sh_first;

    u32 sbase = (u32)__cvta_generic_to_shared(smem);
    const u32 mW  = sbase + MBAR_OFF;
    const u32 mX0 = sbase + MBAR_OFF + 8;
    const u32 mX1 = sbase + MBAR_OFF + 16;
    const u32 aXA = sbase + XA_OFF * 4;
    const u32 aXB = sbase + XB_OFF * 4;

    const int tid = threadIdx.x;
    const int r0  = (tid >> 3) * 4;   // 4 batch rows / thread
    const int u0  = (tid & 7) * 2;    // 2 adjacent units (of 16-unit group)

    // one-time: zero tiles (finite garbage guarantees) + init mbarriers
    {
        float4 z = make_float4(0.f, 0.f, 0.f, 0.f);
        for (int i = tid; i < SMEM_FLOATS / 4; i += NTHR) ((float4*)smem)[i] = z;
        if (tid == 0) {
            mbar_init(mW, 1); mbar_init(mX0, 1); mbar_init(mX1, 1);
            asm volatile("fence.proxy.async.shared::cta;" ::: "memory");
        }
    }
    __syncthreads();
    u32 pw = 0, p0 = 0, p1 = 0;

    for (int w = blockIdx.x; w < NTICK; w += gridDim.x) {
        // ---- decode ticket -> (t, l, cg), diagonal-major ----
        int rem = w, d = 0;
        for (;; ++d) {
            int nd4 = min(min(d + 1, 127 - d), 64) * NSPLIT;
            if (rem < nd4) break;
            rem -= nd4;
        }
        const int cg   = rem & 3;
        const int cell = rem >> 2;
        const int t    = ((d > 63) ? (d - 63) : 0) + cell;
        const int l    = d - t;

        // ---- stage W tile: one 32KB bulk (no deps) ----
        if (tid == 0) {
            mbar_expect(mW, 32768);
            bulk_g2s(sbase + WS_OFF * 4, &g_wt[((size_t)l * 4 + cg) * 8192], 32768, mW);
        }

        float2 bpre[4];
        {
            const float* bias = (l == 0) ? b0 : (bl + (l - 1) * 256);
            #pragma unroll
            for (int g = 0; g < 4; g++)
                bpre[g] = *(const float2*)(bias + g * 64 + cg * 16 + u0);
        }
        u64 accI[4][4], accP[4][4];
        #pragma unroll
        for (int g = 0; g < 4; g++) {
            u64 bs = pack2(bpre[g].x, bpre[g].y);
            #pragma unroll
            for (int i = 0; i < 4; i++) { accI[i][g] = bs; accP[i][g] = 0ULL; }
        }

        const float* hin_base   = (l > 0) ? &g_h[((size_t)t * Ll + (l - 1)) * Bb * Hh] : (const float*)0;
        const float* hprev_base = (t > 0) ? &g_h[((size_t)(t - 1) * Ll + l) * Bb * Hh] : (const float*)0;

        if (l == 0) {
            // X = [h_prev (A) | x at B.col0 | zeros]; W_tiled[0] matches.
            if (tid == 0 && t > 0) {
                polln(&g_flags[(t - 1) * Ll + l]);
                mbar_expect(mX0, 32768);
                bulk_g2s(aXA, hprev_base, 32768, mX0);
            }
            if (tid < 128) XsB[tid * 64] = x[tid * Tt + t];
            if (t == 0) {
                // zero XsA (stale h values would multiply real weights)
                float4 z = make_float4(0.f, 0.f, 0.f, 0.f);
                for (int i = tid; i < 2048; i += NTHR) ((float4*)XsA)[i] = z;
            }
            __syncthreads();                 // x column + optional zeroing visible
            mbar_wait(mW, pw); pw ^= 1;
            if (t > 0) { mbar_wait(mX0, p0); p0 ^= 1; gemm64(XsA, Ws, r0, u0, accI); }
            // x term: Ws row 64 holds W0 row 0
            {
                u64 b2[4];
                #pragma unroll
                for (int g = 0; g < 4; g++) b2[g] = *(const u64*)(Ws + 64 * 64 + g * 16 + u0);
                #pragma unroll
                for (int i = 0; i < 4; i++) {
                    float a = XsB[(r0 + i) * 64];
                    u64 a2 = pack2(a, a);
                    #pragma unroll
                    for (int g = 0; g < 4; g++) fma2(accI[i][g], a2, b2[g]);
                }
            }
        } else if (t == 0) {
            // only h_in half
            if (tid == 0) {
                polln(&g_flags[t * Ll + (l - 1)]);
                mbar_expect(mX0, 32768);
                bulk_g2s(aXA, hin_base, 32768, mX0);
            }
            mbar_wait(mW, pw); pw ^= 1;
            mbar_wait(mX0, p0); p0 ^= 1;
            gemm64(XsA, Ws, r0, u0, accI);
        } else {
            // adaptive dual-half
            const int* fI = &g_flags[t * Ll + (l - 1)];
            const int* fP = &g_flags[(t - 1) * Ll + l];
            if (tid == 0) {
                int a, b;
                for (;;) {
                    a = ldacq(fI); b = ldacq(fP);
                    if (a >= NSPLIT || b >= NSPLIT) break;
                }
                int first = (a >= NSPLIT) ? ((b >= NSPLIT) ? 2 : 0) : 1;
                sh_first = first;
                if (first == 2) {
                    mbar_expect(mX0, 65536);
                    bulk_g2s(aXA, hin_base, 32768, mX0);
                    bulk_g2s(aXB, hprev_base, 32768, mX0);
                } else if (first == 0) {
                    mbar_expect(mX0, 32768);
                    bulk_g2s(aXA, hin_base, 32768, mX0);
                } else {
                    mbar_expect(mX0, 32768);
                    bulk_g2s(aXB, hprev_base, 32768, mX0);
                }
            }
            __syncthreads();
            const int first = sh_first;
            mbar_wait(mW, pw); pw ^= 1;
            mbar_wait(mX0, p0); p0 ^= 1;
            if (first == 2) {
                gemm64(XsA, Ws, r0, u0, accI);
                gemm64(XsB, Ws + 64 * 64, r0, u0, accP);
            } else if (first == 0) {
                gemm64(XsA, Ws, r0, u0, accI);
                if (tid == 0) {
                    polln(fP);
                    mbar_expect(mX1, 32768);
                    bulk_g2s(aXB, hprev_base, 32768, mX1);
                }
                mbar_wait(mX1, p1); p1 ^= 1;
                gemm64(XsB, Ws + 64 * 64, r0, u0, accP);
            } else {
                gemm64(XsB, Ws + 64 * 64, r0, u0, accP);
                if (tid == 0) {
                    polln(fI);
                    mbar_expect(mX1, 32768);
                    bulk_g2s(aXA, hin_base, 32768, mX1);
                }
                mbar_wait(mX1, p1); p1 ^= 1;
                gemm64(XsA, Ws, r0, u0, accI);
            }
        }

        // ---- gates epilogue: z = (bias + zI) + zP (fixed order) ----
        float* cptr = &g_c[(size_t)l * Bb * Hh];
        float* hout = &g_h[((size_t)t * Ll + l) * Bb * Hh];
        #pragma unroll
        for (int i = 0; i < 4; i++) {
            int row = r0 + i;
            int off = row * Hh + cg * 16 + u0;
            float z0[4], z1[4];
            #pragma unroll
            for (int g = 0; g < 4; g++) {
                float iA, iB, pA, pB;
                unpack2(accI[i][g], iA, iB);
                unpack2(accP[i][g], pA, pB);
                z0[g] = iA + pA; z1[g] = iB + pB;
            }
            float cp0 = 0.f, cp1 = 0.f;
            if (t > 0) {
                float2 cp = __ldcg((const float2*)(cptr + off));
                cp0 = cp.x; cp1 = cp.y;
            }
            float c20 = cp0 * sigm(z0[2]) + sigm(z0[0]) * tanhf(z0[1]);
            float c21 = cp1 * sigm(z1[2]) + sigm(z1[0]) * tanhf(z1[1]);
            float h20 = tanhf(c20) * sigm(z0[3]);
            float h21 = tanhf(c21) * sigm(z1[3]);
            __stcg((float2*)(cptr + off), make_float2(c20, c21));
            *(float2*)(hout + off) = make_float2(h20, h21);
        }

        __syncthreads();   // all stores issued; also gates smem reuse next iter
        if (tid == 0) rel_add(&g_flags[t * Ll + l]);
    }
}

// pred[b,t] = relu(h[t][63][b][:] . Wd[t] + bd[t]); per-t squared-error partials.
__global__ void dense_kernel(const float* __restrict__ labels, const float* __restrict__ Wd,
                             const float* __restrict__ bd, float* __restrict__ out)
{
    int t = blockIdx.x;
    int b = threadIdx.x;
    __shared__ float wd[64];
    __shared__ float red[128];
    if (b < 64) wd[b] = Wd[t * 64 + b];
    __syncthreads();
    const float* hrow = &g_h[(((size_t)t * Ll + 63) * Bb + b) * Hh];
    float acc = 0.f;
    #pragma unroll
    for (int u = 0; u < 64; u++) acc += hrow[u] * wd[u];
    float p = acc + bd[t];
    p = (p > 0.f) ? p : 0.f;
    out[b * 64 + t] = p;
    float e = labels[b * 64 + t] - p;
    red[b] = e * e;
    __syncthreads();
    for (int s = 64; s > 0; s >>= 1) {
        if (b < s) red[b] += red[b + s];
        __syncthreads();
    }
    if (b == 0) g_partial[t] = red[0];
}

__global__ void loss_kernel(float* out, int out_size)
{
    __shared__ float red[64];
    int tid = threadIdx.x;
    red[tid] = g_partial[tid];
    __syncthreads();
    for (int s = 32; s > 0; s >>= 1) {
        if (tid < s) red[tid] += red[tid + s];
        __syncthreads();
    }
    if (tid == 0 && out_size > Bb * Tt) out[Bb * Tt] = red[0] / (float)(Bb * Tt);
}

extern "C" void kernel_launch(void* const* d_in, const int* in_sizes, int n_in,
                              void* d_out, int out_size) {
    const float* x      = (const float*)d_in[0];
    const float* labels = (const float*)d_in[1];
    const float* W0     = (const float*)d_in[2];
    const float* b0     = (const float*)d_in[3];
    const float* Wl     = (const float*)d_in[4];
    const float* bl     = (const float*)d_in[5];
    const float* Wd     = (const float*)d_in[6];
    const float* bd     = (const float*)d_in[7];
    float* out = (float*)d_out;

    cudaFuncSetAttribute(wave_kernel, cudaFuncAttributeMaxDynamicSharedMemorySize, SMEM_BYTES);

    init_kernel<<<16, 256>>>();
    wtile_kernel<<<8192, 256>>>(W0, Wl);
    wave_kernel<<<NCTA, NTHR, SMEM_BYTES>>>(x, b0, bl);
    dense_kernel<<<64, 128>>>(labels, Wd, bd, out);
    loss_kernel<<<1, 64>>>(out, out_size);
}